// round 14
// baseline (speedup 1.0000x reference)
#include <cuda_runtime.h>
#include <cstdint>
#include <math.h>

// Problem dims
#define NB   64
#define SEQ  512
#define IMG  3200
#define FC   64
#define HID  256
#define G4   1024

// Output layout (floats): [logprobs 64*512*2 | output_feats 64*512*256 | selected 64*256]
#define OFF_LP  0
#define OFF_OF  (NB*SEQ*2)
#define OFF_SEL (OFF_OF + NB*SEQ*HID)

// ---------------- scratch ----------------
__device__ float g_emb[NB * FC];
__device__ float g_fuse[NB * SEQ * FC];

// ---------------- helpers ----------------
__device__ __forceinline__ float2 ffma2(float2 a, float2 b, float2 c) {
    unsigned long long ua = *reinterpret_cast<unsigned long long*>(&a);
    unsigned long long ub = *reinterpret_cast<unsigned long long*>(&b);
    unsigned long long uc = *reinterpret_cast<unsigned long long*>(&c);
    unsigned long long ud;
    asm("fma.rn.f32x2 %0, %1, %2, %3;" : "=l"(ud) : "l"(ua), "l"(ub), "l"(uc));
    return *reinterpret_cast<float2*>(&ud);
}

__device__ __forceinline__ uint32_t smem_u32(const void* p) {
    uint32_t a;
    asm("{ .reg .u64 t; cvta.to.shared.u64 t, %1; cvt.u32.u64 %0, t; }" : "=r"(a) : "l"(p));
    return a;
}

__device__ __forceinline__ float sigm(float x)  { return 1.0f / (1.0f + __expf(-x)); }
__device__ __forceinline__ float tanh_(float x) { return 1.0f - 2.0f / (__expf(2.0f * x) + 1.0f); }

__device__ __forceinline__ void mbar_init(uint32_t a, uint32_t c) {
    asm volatile("mbarrier.init.shared.b64 [%0], %1;" :: "r"(a), "r"(c) : "memory");
}
__device__ __forceinline__ void mbar_expect_tx(uint32_t a, uint32_t tx) {
    asm volatile("mbarrier.arrive.expect_tx.shared.b64 _, [%0], %1;" :: "r"(a), "r"(tx) : "memory");
}
__device__ __forceinline__ void mbar_wait(uint32_t a, uint32_t phase) {
    asm volatile(
        "{\n\t"
        ".reg .pred P;\n\t"
        "WL_%=:\n\t"
        "mbarrier.try_wait.parity.acquire.cta.shared::cta.b64 P, [%0], %1, 0x989680;\n\t"
        "@P bra WD_%=;\n\t"
        "bra WL_%=;\n\t"
        "WD_%=:\n\t"
        "}" :: "r"(a), "r"(phase) : "memory");
}
__device__ __forceinline__ uint32_t mapa_u32(uint32_t a, uint32_t r) {
    uint32_t ra;
    asm("mapa.shared::cluster.u32 %0, %1, %2;" : "=r"(ra) : "r"(a), "r"(r));
    return ra;
}
__device__ __forceinline__ void st_async_f32(uint32_t dst, float v, uint32_t rbar) {
    asm volatile("st.async.shared::cluster.mbarrier::complete_tx::bytes.b32 [%0], %1, [%2];"
                 :: "r"(dst), "r"(__float_as_uint(v)), "r"(rbar) : "memory");
}

// ---------------- kernel 1: emb ----------------
__global__ void emb_kernel(const float* __restrict__ phr,
                           const float* __restrict__ Wp,
                           const float* __restrict__ bp) {
    __shared__ float ps[304];
    int b = blockIdx.x, tid = threadIdx.x;
    for (int i = tid; i < 300; i += 64) ps[i] = phr[b * 300 + i];
    __syncthreads();
    float acc = bp[tid];
#pragma unroll 4
    for (int k = 0; k < 300; k++) acc += ps[k] * Wp[k * 64 + tid];
    g_emb[b * 64 + tid] = fmaxf(acc, 0.0f);
}

// ---------------- kernel 2: fuse ----------------
__global__ __launch_bounds__(256) void fuse_kernel(const float* __restrict__ img,
                                                   const float* __restrict__ Wc,
                                                   const float* __restrict__ bc) {
    __shared__ float As[2][16][132];
    __shared__ float Bs[2][16][64];
    __shared__ float es[64];

    const int tid = threadIdx.x;
    const int tx = tid & 15, ty = tid >> 4;
    const int row0 = blockIdx.x * 128;
    const int batch = row0 >> 9;

    if (tid < 64) es[tid] = g_emb[batch * 64 + tid];

    float bcr[4];
#pragma unroll
    for (int c = 0; c < 4; c++) bcr[c] = bc[tx * 4 + c];

    float2 acc[4][4];
#pragma unroll
    for (int mp = 0; mp < 4; mp++)
#pragma unroll
        for (int c = 0; c < 4; c++) acc[mp][c] = make_float2(0.f, 0.f);

    auto loadA = [&](int s, int kk) {
#pragma unroll
        for (int i = 0; i < 2; i++) {
            int id = tid * 2 + i;
            int m = id >> 2, q = id & 3;
            float4 v = *reinterpret_cast<const float4*>(img + (size_t)(row0 + m) * IMG + kk + q * 4);
            As[s][q * 4 + 0][m] = v.x;
            As[s][q * 4 + 1][m] = v.y;
            As[s][q * 4 + 2][m] = v.z;
            As[s][q * 4 + 3][m] = v.w;
        }
    };
    auto loadB = [&](int s, int kk) {
        int k = tid >> 4, q = tid & 15;
        *reinterpret_cast<float4*>(&Bs[s][k][q * 4]) =
            *reinterpret_cast<const float4*>(Wc + (size_t)(kk + k) * 64 + q * 4);
    };

    loadA(0, 0);
    loadB(0, 0);
    __syncthreads();

    for (int ch = 0; ch < 200; ch++) {
        int s = ch & 1;
        if (ch + 1 < 200) { loadA(s ^ 1, (ch + 1) * 16); loadB(s ^ 1, (ch + 1) * 16); }
#pragma unroll
        for (int k = 0; k < 16; k++) {
            float4 b4 = *reinterpret_cast<const float4*>(&Bs[s][k][tx * 4]);
            float4 a0 = *reinterpret_cast<const float4*>(&As[s][k][ty * 8]);
            float4 a1 = *reinterpret_cast<const float4*>(&As[s][k][ty * 8 + 4]);
            float2 aa[4] = { {a0.x, a0.y}, {a0.z, a0.w}, {a1.x, a1.y}, {a1.z, a1.w} };
            float  bb[4] = { b4.x, b4.y, b4.z, b4.w };
#pragma unroll
            for (int c = 0; c < 4; c++) {
                float2 bv = make_float2(bb[c], bb[c]);
#pragma unroll
                for (int mp = 0; mp < 4; mp++) acc[mp][c] = ffma2(aa[mp], bv, acc[mp][c]);
            }
        }
        __syncthreads();
    }

    float sc[4];
#pragma unroll
    for (int c = 0; c < 4; c++) sc[c] = es[tx * 4 + c];

#pragma unroll
    for (int mp = 0; mp < 4; mp++) {
        float4 r0v, r1v;
        r0v.x = fmaxf(acc[mp][0].x + bcr[0], 0.f) * sc[0];
        r0v.y = fmaxf(acc[mp][1].x + bcr[1], 0.f) * sc[1];
        r0v.z = fmaxf(acc[mp][2].x + bcr[2], 0.f) * sc[2];
        r0v.w = fmaxf(acc[mp][3].x + bcr[3], 0.f) * sc[3];
        r1v.x = fmaxf(acc[mp][0].y + bcr[0], 0.f) * sc[0];
        r1v.y = fmaxf(acc[mp][1].y + bcr[1], 0.f) * sc[1];
        r1v.z = fmaxf(acc[mp][2].y + bcr[2], 0.f) * sc[2];
        r1v.w = fmaxf(acc[mp][3].y + bcr[3], 0.f) * sc[3];
        int r = row0 + ty * 8 + mp * 2;
        *reinterpret_cast<float4*>(g_fuse + (size_t)r * 64 + tx * 4)       = r0v;
        *reinterpret_cast<float4*>(g_fuse + (size_t)(r + 1) * 64 + tx * 4) = r1v;
    }
}

// ---------------- kernel 3: LSTM (R13 core, TWO interleaved batch-groups/cluster) ----------------
// 8 clusters x 8 CTAs (grid 64), 512 threads. Each cluster runs groups A and B
// (4 batches each) with duplicated hbuf/xs/gsm/mbarriers and SHARED W registers.
// Per iteration: [waitA gemmA relayA actA sendA xaccA][waitB gemmB relayB actB sendB xaccB]
// so each group's DSMEM fabric latency is hidden under the other group's compute.
#define HB1 1088                        // floats per h buffer (4*4*68)
#define HBUF_BYTES (HB1 * 4)            // 4352

__global__ void __cluster_dims__(8, 1, 1) __launch_bounds__(512, 1)
lstm_kernel(const float* __restrict__ Whh,
            const float* __restrict__ Wih,
            const float* __restrict__ bih,
            const float* __restrict__ bhh,
            float* __restrict__ of) {
    extern __shared__ float sm[];
    // layout (floats): bars 8 | hbufA 2176 | hbufB 2176 | xsA 544 | xsB 544 | gsmA 512 | gsmB 512 | Wi_s 8192
    float* hbufA = sm + 8;
    float* hbufB = hbufA + 2176;
    float* xsA   = hbufB + 2176;
    float* xsB   = xsA + 544;
    float* gsmA  = xsB + 544;
    float* gsmB  = gsmA + 512;
    float* Wi_s  = gsmB + 512;

    const int tid  = threadIdx.x;
    const int warp = tid >> 5, lane = tid & 31;
    const int gl = lane & 7, q = lane >> 3;
    const int g  = warp * 8 + gl;          // gate slot 0..127
    const int rank   = blockIdx.x & 7;
    const int batchA0 = (blockIdx.x >> 3) * 8;       // group A batches [A0, A0+4)
    const int col = ((g >> 5) << 8) + (rank << 5) + (g & 31);

    // ---- stage W_ih slice coalesced (init only) ----
    for (int i = tid; i < 8192; i += 512) {
        int k = i >> 7, c = i & 127;
        int cg = ((c >> 5) << 8) + (rank << 5) + (c & 31);
        Wi_s[k * 128 + c] = Wih[(size_t)k * G4 + cg];
    }

    // ---- W_hh registers (exact R2/R13) ----
    float2 Wr[32];
    {
        const float* wp = Whh + (size_t)(q * 64) * G4 + col;
#pragma unroll
        for (int j = 0; j < 32; j++) {
            Wr[j].x = wp[(size_t)(2 * j) * G4];
            Wr[j].y = wp[(size_t)(2 * j + 1) * G4];
        }
    }
    float bg = (q == 0) ? (bih[col] + bhh[col]) : 0.0f;

    const uint32_t bar0 = smem_u32(sm);     // A0 @+0, A1 @+8, B0 @+16, B1 @+24
    if (tid == 0) {
#pragma unroll
        for (int i = 0; i < 4; i++) {
            mbar_init(bar0 + i * 8, 1);
            mbar_expect_tx(bar0 + i * 8, 4096);
        }
    }
    // prefetch x for t=0,1: threads 0-127 group A, 128-255 group B
    if (tid < 256) {
        int grp = tid >> 7;
        int e = tid & 127;
        int buf = e >> 6, f = e & 63;
        int b = f >> 4, j = f & 15;
        float* xs = grp ? xsB : xsA;
        int batch = (grp ? batchA0 + 4 : batchA0) + b;
        *reinterpret_cast<float4*>(xs + buf * 272 + b * 68 + j * 4) =
            *reinterpret_cast<const float4*>(g_fuse + ((size_t)batch * SEQ + buf) * FC + j * 4);
    }
    __syncthreads();

    // ---- W_ih registers (shared by both groups) ----
    float2 Wir[8];
#pragma unroll
    for (int j = 0; j < 8; j++) {
        int k = q * 16 + 2 * j;
        Wir[j].x = Wi_s[k * 128 + g];
        Wir[j].y = Wi_s[(k + 1) * 128 + g];
    }

    asm volatile("barrier.cluster.arrive.aligned;" ::: "memory");
    asm volatile("barrier.cluster.wait.aligned;"   ::: "memory");

    // producer identity (tid < 128)
    const int bb = tid >> 5, ub = tid & 31;
    const int kglob = (rank << 5) + ub;
    uint32_t dstA0 = 0;
    if (tid < 128)
        dstA0 = smem_u32(hbufA + bb * 272 + (kglob >> 6) * 68 + (kglob & 63));
    const uint32_t dstB_off = (uint32_t)((hbufB - hbufA) * 4);   // 8704 B

    float* ofA = of + (size_t)(batchA0 + bb) * (SEQ * HID) + (rank << 5) + ub;
    float* ofB = ofA + (size_t)4 * SEQ * HID;

    // ---- xacc for t=0, both groups ----
    float xaccA[4], xaccB[4];
#pragma unroll
    for (int b = 0; b < 4; b++) {
        float2 a = make_float2(bg * 0.5f, bg * 0.5f);
        const float* xp = xsA + b * 68 + q * 16;
#pragma unroll
        for (int i = 0; i < 8; i++)
            a = ffma2(Wir[i], *reinterpret_cast<const float2*>(xp + 2 * i), a);
        xaccA[b] = a.x + a.y;
        float2 c2 = make_float2(bg * 0.5f, bg * 0.5f);
        const float* xq = xsB + b * 68 + q * 16;
#pragma unroll
        for (int i = 0; i < 8; i++)
            c2 = ffma2(Wir[i], *reinterpret_cast<const float2*>(xq + 2 * i), c2);
        xaccB[b] = c2.x + c2.y;
    }

    float cregA = 0.0f, cregB = 0.0f;
    int phA0 = 0, phA1 = 0, phB0 = 0, phB1 = 0;

    for (int t = 0; t < SEQ; t++) {
        const int p = t & 1;

        // ================= GROUP A =================
        {
            float val[4];
#pragma unroll
            for (int b = 0; b < 4; b++) val[b] = xaccA[b];

            if (t > 0) {
                uint32_t barp = bar0 + p * 8;
                int par = p ? phA1 : phA0;
                mbar_wait(barp, par);
                if (p) phA1 ^= 1; else phA0 ^= 1;
                if (tid == 0) mbar_expect_tx(barp, 4096);

#pragma unroll
                for (int b = 0; b < 4; b++) {
                    float2 acc = make_float2(0.f, 0.f);
                    const float* hp = hbufA + p * HB1 + b * 272 + q * 68;
#pragma unroll
                    for (int j = 0; j < 16; j++) {
                        float4 h4 = *reinterpret_cast<const float4*>(hp + j * 4);
                        acc = ffma2(Wr[2 * j],     make_float2(h4.x, h4.y), acc);
                        acc = ffma2(Wr[2 * j + 1], make_float2(h4.z, h4.w), acc);
                    }
                    val[b] += acc.x + acc.y;
                }
            }
#pragma unroll
            for (int b = 0; b < 4; b++) {
                val[b] += __shfl_xor_sync(0xffffffffu, val[b], 8);
                val[b] += __shfl_xor_sync(0xffffffffu, val[b], 16);
            }
            if (lane < 8)
                *reinterpret_cast<float4*>(gsmA + (warp * 8 + lane) * 4) =
                    make_float4(val[0], val[1], val[2], val[3]);
            __syncthreads();

            if (tid < 128) {
                float gi = gsmA[ub * 4 + bb];
                float gf = gsmA[(32 + ub) * 4 + bb];
                float gg = gsmA[(64 + ub) * 4 + bb];
                float go = gsmA[(96 + ub) * 4 + bb];
                float tg = tanh_(gg);
                cregA = sigm(gf) * cregA + sigm(gi) * tg;
                float h = sigm(go) * tanh_(cregA);

                if (t + 1 < SEQ) {
                    uint32_t doff = dstA0 + (p ^ 1) * HBUF_BYTES;
                    uint32_t boff = bar0 + (p ^ 1) * 8;
#pragma unroll
                    for (int r = 0; r < 8; r++)
                        st_async_f32(mapa_u32(doff, r), h, mapa_u32(boff, r));
                }
                ofA[(size_t)t * HID] = h;
            } else if (tid < 192 && t + 2 < SEQ) {
                int e = tid - 128;
                int b = e >> 4, j = e & 15;
                *reinterpret_cast<float4*>(xsA + p * 272 + b * 68 + j * 4) =
                    *reinterpret_cast<const float4*>(g_fuse + ((size_t)(batchA0 + b) * SEQ + (t + 2)) * FC + j * 4);
            }
            if (t + 1 < SEQ) {
#pragma unroll
                for (int b = 0; b < 4; b++) {
                    float2 a = make_float2(bg * 0.5f, bg * 0.5f);
                    const float* xp = xsA + (p ^ 1) * 272 + b * 68 + q * 16;
#pragma unroll
                    for (int i = 0; i < 8; i++)
                        a = ffma2(Wir[i], *reinterpret_cast<const float2*>(xp + 2 * i), a);
                    xaccA[b] = a.x + a.y;
                }
            }
        }

        // ================= GROUP B =================
        {
            float val[4];
#pragma unroll
            for (int b = 0; b < 4; b++) val[b] = xaccB[b];

            if (t > 0) {
                uint32_t barp = bar0 + 16 + p * 8;
                int par = p ? phB1 : phB0;
                mbar_wait(barp, par);
                if (p) phB1 ^= 1; else phB0 ^= 1;
                if (tid == 0) mbar_expect_tx(barp, 4096);

#pragma unroll
                for (int b = 0; b < 4; b++) {
                    float2 acc = make_float2(0.f, 0.f);
                    const float* hp = hbufB + p * HB1 + b * 272 + q * 68;
#pragma unroll
                    for (int j = 0; j < 16; j++) {
                        float4 h4 = *reinterpret_cast<const float4*>(hp + j * 4);
                        acc = ffma2(Wr[2 * j],     make_float2(h4.x, h4.y), acc);
                        acc = ffma2(Wr[2 * j + 1], make_float2(h4.z, h4.w), acc);
                    }
                    val[b] += acc.x + acc.y;
                }
            }
#pragma unroll
            for (int b = 0; b < 4; b++) {
                val[b] += __shfl_xor_sync(0xffffffffu, val[b], 8);
                val[b] += __shfl_xor_sync(0xffffffffu, val[b], 16);
            }
            if (lane < 8)
                *reinterpret_cast<float4*>(gsmB + (warp * 8 + lane) * 4) =
                    make_float4(val[0], val[1], val[2], val[3]);
            __syncthreads();

            if (tid < 128) {
                float gi = gsmB[ub * 4 + bb];
                float gf = gsmB[(32 + ub) * 4 + bb];
                float gg = gsmB[(64 + ub) * 4 + bb];
                float go = gsmB[(96 + ub) * 4 + bb];
                float tg = tanh_(gg);
                cregB = sigm(gf) * cregB + sigm(gi) * tg;
                float h = sigm(go) * tanh_(cregB);

                if (t + 1 < SEQ) {
                    uint32_t doff = dstA0 + dstB_off + (p ^ 1) * HBUF_BYTES;
                    uint32_t boff = bar0 + 16 + (p ^ 1) * 8;
#pragma unroll
                    for (int r = 0; r < 8; r++)
                        st_async_f32(mapa_u32(doff, r), h, mapa_u32(boff, r));
                }
                ofB[(size_t)t * HID] = h;
            } else if (tid < 192 && t + 2 < SEQ) {
                int e = tid - 128;
                int b = e >> 4, j = e & 15;
                *reinterpret_cast<float4*>(xsB + p * 272 + b * 68 + j * 4) =
                    *reinterpret_cast<const float4*>(g_fuse + ((size_t)(batchA0 + 4 + b) * SEQ + (t + 2)) * FC + j * 4);
            }
            if (t + 1 < SEQ) {
#pragma unroll
                for (int b = 0; b < 4; b++) {
                    float2 a = make_float2(bg * 0.5f, bg * 0.5f);
                    const float* xp = xsB + (p ^ 1) * 272 + b * 68 + q * 16;
#pragma unroll
                    for (int i = 0; i < 8; i++)
                        a = ffma2(Wir[i], *reinterpret_cast<const float2*>(xp + 2 * i), a);
                    xaccB[b] = a.x + a.y;
                }
            }
        }
    }

    asm volatile("barrier.cluster.arrive.aligned;" ::: "memory");
    asm volatile("barrier.cluster.wait.aligned;"   ::: "memory");
}

// ---------------- kernel 4: classifier + log_softmax ----------------
__global__ __launch_bounds__(256) void cls_kernel(const float* __restrict__ of,
                                                  const float* __restrict__ W1,
                                                  const float* __restrict__ b1,
                                                  const float* __restrict__ W2,
                                                  const float* __restrict__ b2,
                                                  float* __restrict__ lp) {
    __shared__ float As[2][16][132];
    __shared__ float Bs[2][16][64];

    const int tid = threadIdx.x;
    const int tx = tid & 15, ty = tid >> 4;
    const int row0 = blockIdx.x * 128;

    float b1r[4], w20[4], w21[4];
#pragma unroll
    for (int c = 0; c < 4; c++) {
        int f = tx * 4 + c;
        b1r[c] = b1[f];
        w20[c] = W2[f * 2 + 0];
        w21[c] = W2[f * 2 + 1];
    }
    const float bb0 = b2[0], bb1 = b2[1];

    float2 acc[4][4];
#pragma unroll
    for (int mp = 0; mp < 4; mp++)
#pragma unroll
        for (int c = 0; c < 4; c++) acc[mp][c] = make_float2(0.f, 0.f);

    auto loadA = [&](int s, int kk) {
#pragma unroll
        for (int i = 0; i < 2; i++) {
            int id = tid * 2 + i;
            int m = id >> 2, q = id & 3;
            float4 v = *reinterpret_cast<const float4*>(of + (size_t)(row0 + m) * HID + kk + q * 4);
            As[s][q * 4 + 0][m] = v.x;
            As[s][q * 4 + 1][m] = v.y;
            As[s][q * 4 + 2][m] = v.z;
            As[s][q * 4 + 3][m] = v.w;
        }
    };
    auto loadB = [&](int s, int kk) {
        int k = tid >> 4, q = tid & 15;
        *reinterpret_cast<float4*>(&Bs[s][k][q * 4]) =
            *reinterpret_cast<const float4*>(W1 + (size_t)(kk + k) * 64 + q * 4);
    };

    loadA(0, 0);
    loadB(0, 0);
    __syncthreads();

    for (int ch = 0; ch < 16; ch++) {
        int s = ch & 1;
        if (ch + 1 < 16) { loadA(s ^ 1, (ch + 1) * 16); loadB(s ^ 1, (ch + 1) * 16); }
#pragma unroll
        for (int k = 0; k < 16; k++) {
            float4 b4 = *reinterpret_cast<const float4*>(&Bs[s][k][tx * 4]);
            float4 a0 = *reinterpret_cast<const float4*>(&As[s][k][ty * 8]);
            float4 a1 = *reinterpret_cast<const float4*>(&As[s][k][ty * 8 + 4]);
            float2 aa[4] = { {a0.x, a0.y}, {a0.z, a0.w}, {a1.x, a1.y}, {a1.z, a1.w} };
            float  bb[4] = { b4.x, b4.y, b4.z, b4.w };
#pragma unroll
            for (int c = 0; c < 4; c++) {
                float2 bv = make_float2(bb[c], bb[c]);
#pragma unroll
                for (int mp = 0; mp < 4; mp++) acc[mp][c] = ffma2(aa[mp], bv, acc[mp][c]);
            }
        }
        __syncthreads();
    }

#pragma unroll
    for (int mp = 0; mp < 4; mp++) {
#pragma unroll
        for (int half = 0; half < 2; half++) {
            float p0 = 0.f, p1 = 0.f;
#pragma unroll
            for (int c = 0; c < 4; c++) {
                float vv = half ? acc[mp][c].y : acc[mp][c].x;
                float hd = fmaxf(vv + b1r[c], 0.f);
                p0 += hd * w20[c];
                p1 += hd * w21[c];
            }
#pragma unroll
            for (int s = 1; s < 16; s <<= 1) {
                p0 += __shfl_xor_sync(0xffffffffu, p0, s);
                p1 += __shfl_xor_sync(0xffffffffu, p1, s);
            }
            if ((tid & 15) == 0) {
                float l0 = p0 + bb0, l1 = p1 + bb1;
                float m = fmaxf(l0, l1);
                float lse = m + logf(expf(l0 - m) + expf(l1 - m));
                int row = row0 + ty * 8 + mp * 2 + half;
                lp[row * 2 + 0] = l0 - lse;
                lp[row * 2 + 1] = l1 - lse;
            }
        }
    }
}

// ---------------- kernel 5: gather selected ----------------
__global__ void sel_kernel(const int* __restrict__ ix, const float* __restrict__ of,
                           float* __restrict__ sel) {
    int b = blockIdx.x;
    int t = ix[b];
    sel[b * HID + threadIdx.x] = of[(size_t)b * (SEQ * HID) + (size_t)t * HID + threadIdx.x];
}

// ---------------- launch ----------------
extern "C" void kernel_launch(void* const* d_in, const int* in_sizes, int n_in,
                              void* d_out, int out_size) {
    const float* img = (const float*)d_in[0];
    const float* phr = (const float*)d_in[1];
    const int*   six = (const int*)d_in[3];
    const float* Wc  = (const float*)d_in[4];
    const float* bc  = (const float*)d_in[5];
    const float* Wp  = (const float*)d_in[6];
    const float* bp  = (const float*)d_in[7];
    const float* Wih = (const float*)d_in[8];
    const float* bih = (const float*)d_in[9];
    const float* Whh = (const float*)d_in[10];
    const float* bhh = (const float*)d_in[11];
    const float* W1  = (const float*)d_in[12];
    const float* b1  = (const float*)d_in[13];
    const float* W2  = (const float*)d_in[14];
    const float* b2  = (const float*)d_in[15];

    float* out = (float*)d_out;
    float* lp  = out + OFF_LP;
    float* of  = out + OFF_OF;
    float* sel = out + OFF_SEL;

    const int smem_bytes = (8 + 2176*2 + 544*2 + 512*2 + 8192) * 4;   // 58656
    cudaFuncSetAttribute(lstm_kernel, cudaFuncAttributeMaxDynamicSharedMemorySize, smem_bytes);

    emb_kernel <<<64, 64>>>(phr, Wp, bp);
    fuse_kernel<<<256, 256>>>(img, Wc, bc);
    lstm_kernel<<<64, 512, smem_bytes>>>(Whh, Wih, bih, bhh, of);
    cls_kernel <<<256, 256>>>(of, W1, b1, W2, b2, lp);
    sel_kernel <<<64, 256>>>(six, of, sel);
}

// round 15
// speedup vs baseline: 1.2880x; 1.2880x over previous
#include <cuda_runtime.h>
#include <cstdint>
#include <math.h>

// Problem dims
#define NB   64
#define SEQ  512
#define IMG  3200
#define FC   64
#define HID  256
#define G4   1024

// Output layout (floats): [logprobs 64*512*2 | output_feats 64*512*256 | selected 64*256]
#define OFF_LP  0
#define OFF_OF  (NB*SEQ*2)
#define OFF_SEL (OFF_OF + NB*SEQ*HID)

// ---------------- scratch ----------------
__device__ float g_emb[NB * FC];
__device__ float g_fuse[NB * SEQ * FC];

// ---------------- helpers ----------------
__device__ __forceinline__ float2 ffma2(float2 a, float2 b, float2 c) {
    unsigned long long ua = *reinterpret_cast<unsigned long long*>(&a);
    unsigned long long ub = *reinterpret_cast<unsigned long long*>(&b);
    unsigned long long uc = *reinterpret_cast<unsigned long long*>(&c);
    unsigned long long ud;
    asm("fma.rn.f32x2 %0, %1, %2, %3;" : "=l"(ud) : "l"(ua), "l"(ub), "l"(uc));
    return *reinterpret_cast<float2*>(&ud);
}

__device__ __forceinline__ uint32_t smem_u32(const void* p) {
    uint32_t a;
    asm("{ .reg .u64 t; cvta.to.shared.u64 t, %1; cvt.u32.u64 %0, t; }" : "=r"(a) : "l"(p));
    return a;
}

// HW tanh (MUFU.TANH, sm_75+): 1 op instead of expf chains.
__device__ __forceinline__ float tanh_hw(float x) {
    float y;
    asm("tanh.approx.f32 %0, %1;" : "=f"(y) : "f"(x));
    return y;
}
__device__ __forceinline__ float sigm(float x)  { return fmaf(0.5f, tanh_hw(0.5f * x), 0.5f); }
__device__ __forceinline__ float tanh_(float x) { return tanh_hw(x); }

__device__ __forceinline__ void mbar_init(uint32_t a, uint32_t c) {
    asm volatile("mbarrier.init.shared.b64 [%0], %1;" :: "r"(a), "r"(c) : "memory");
}
__device__ __forceinline__ void mbar_expect_tx(uint32_t a, uint32_t tx) {
    asm volatile("mbarrier.arrive.expect_tx.shared.b64 _, [%0], %1;" :: "r"(a), "r"(tx) : "memory");
}
__device__ __forceinline__ void mbar_wait(uint32_t a, uint32_t phase) {
    asm volatile(
        "{\n\t"
        ".reg .pred P;\n\t"
        "WL_%=:\n\t"
        "mbarrier.try_wait.parity.acquire.cta.shared::cta.b64 P, [%0], %1, 0x989680;\n\t"
        "@P bra WD_%=;\n\t"
        "bra WL_%=;\n\t"
        "WD_%=:\n\t"
        "}" :: "r"(a), "r"(phase) : "memory");
}
__device__ __forceinline__ uint32_t mapa_u32(uint32_t a, uint32_t r) {
    uint32_t ra;
    asm("mapa.shared::cluster.u32 %0, %1, %2;" : "=r"(ra) : "r"(a), "r"(r));
    return ra;
}
__device__ __forceinline__ void st_async_f32(uint32_t dst, float v, uint32_t rbar) {
    asm volatile("st.async.shared::cluster.mbarrier::complete_tx::bytes.b32 [%0], %1, [%2];"
                 :: "r"(dst), "r"(__float_as_uint(v)), "r"(rbar) : "memory");
}

// ---------------- kernel 1: emb ----------------
__global__ void emb_kernel(const float* __restrict__ phr,
                           const float* __restrict__ Wp,
                           const float* __restrict__ bp) {
    __shared__ float ps[304];
    int b = blockIdx.x, tid = threadIdx.x;
    for (int i = tid; i < 300; i += 64) ps[i] = phr[b * 300 + i];
    __syncthreads();
    float acc = bp[tid];
#pragma unroll 4
    for (int k = 0; k < 300; k++) acc += ps[k] * Wp[k * 64 + tid];
    g_emb[b * 64 + tid] = fmaxf(acc, 0.0f);
}

// ---------------- kernel 2: fuse ----------------
__global__ __launch_bounds__(256) void fuse_kernel(const float* __restrict__ img,
                                                   const float* __restrict__ Wc,
                                                   const float* __restrict__ bc) {
    __shared__ float As[2][16][132];
    __shared__ float Bs[2][16][64];
    __shared__ float es[64];

    const int tid = threadIdx.x;
    const int tx = tid & 15, ty = tid >> 4;
    const int row0 = blockIdx.x * 128;
    const int batch = row0 >> 9;

    if (tid < 64) es[tid] = g_emb[batch * 64 + tid];

    float bcr[4];
#pragma unroll
    for (int c = 0; c < 4; c++) bcr[c] = bc[tx * 4 + c];

    float2 acc[4][4];
#pragma unroll
    for (int mp = 0; mp < 4; mp++)
#pragma unroll
        for (int c = 0; c < 4; c++) acc[mp][c] = make_float2(0.f, 0.f);

    auto loadA = [&](int s, int kk) {
#pragma unroll
        for (int i = 0; i < 2; i++) {
            int id = tid * 2 + i;
            int m = id >> 2, q = id & 3;
            float4 v = *reinterpret_cast<const float4*>(img + (size_t)(row0 + m) * IMG + kk + q * 4);
            As[s][q * 4 + 0][m] = v.x;
            As[s][q * 4 + 1][m] = v.y;
            As[s][q * 4 + 2][m] = v.z;
            As[s][q * 4 + 3][m] = v.w;
        }
    };
    auto loadB = [&](int s, int kk) {
        int k = tid >> 4, q = tid & 15;
        *reinterpret_cast<float4*>(&Bs[s][k][q * 4]) =
            *reinterpret_cast<const float4*>(Wc + (size_t)(kk + k) * 64 + q * 4);
    };

    loadA(0, 0);
    loadB(0, 0);
    __syncthreads();

    for (int ch = 0; ch < 200; ch++) {
        int s = ch & 1;
        if (ch + 1 < 200) { loadA(s ^ 1, (ch + 1) * 16); loadB(s ^ 1, (ch + 1) * 16); }
#pragma unroll
        for (int k = 0; k < 16; k++) {
            float4 b4 = *reinterpret_cast<const float4*>(&Bs[s][k][tx * 4]);
            float4 a0 = *reinterpret_cast<const float4*>(&As[s][k][ty * 8]);
            float4 a1 = *reinterpret_cast<const float4*>(&As[s][k][ty * 8 + 4]);
            float2 aa[4] = { {a0.x, a0.y}, {a0.z, a0.w}, {a1.x, a1.y}, {a1.z, a1.w} };
            float  bb[4] = { b4.x, b4.y, b4.z, b4.w };
#pragma unroll
            for (int c = 0; c < 4; c++) {
                float2 bv = make_float2(bb[c], bb[c]);
#pragma unroll
                for (int mp = 0; mp < 4; mp++) acc[mp][c] = ffma2(aa[mp], bv, acc[mp][c]);
            }
        }
        __syncthreads();
    }

    float sc[4];
#pragma unroll
    for (int c = 0; c < 4; c++) sc[c] = es[tx * 4 + c];

#pragma unroll
    for (int mp = 0; mp < 4; mp++) {
        float4 r0v, r1v;
        r0v.x = fmaxf(acc[mp][0].x + bcr[0], 0.f) * sc[0];
        r0v.y = fmaxf(acc[mp][1].x + bcr[1], 0.f) * sc[1];
        r0v.z = fmaxf(acc[mp][2].x + bcr[2], 0.f) * sc[2];
        r0v.w = fmaxf(acc[mp][3].x + bcr[3], 0.f) * sc[3];
        r1v.x = fmaxf(acc[mp][0].y + bcr[0], 0.f) * sc[0];
        r1v.y = fmaxf(acc[mp][1].y + bcr[1], 0.f) * sc[1];
        r1v.z = fmaxf(acc[mp][2].y + bcr[2], 0.f) * sc[2];
        r1v.w = fmaxf(acc[mp][3].y + bcr[3], 0.f) * sc[3];
        int r = row0 + ty * 8 + mp * 2;
        *reinterpret_cast<float4*>(g_fuse + (size_t)r * 64 + tx * 4)       = r0v;
        *reinterpret_cast<float4*>(g_fuse + (size_t)(r + 1) * 64 + tx * 4) = r1v;
    }
}

// ---------------- kernel 3: LSTM (R13 exact; HW tanh activations) ----------------
#define PADQ 68
#define HBUF_BYTES (4 * 4 * PADQ * 4)   // one h buffer: 4352 B

__global__ void __cluster_dims__(8, 1, 1) __launch_bounds__(512, 1)
lstm_kernel(const float* __restrict__ Whh,
            const float* __restrict__ Wih,
            const float* __restrict__ bih,
            const float* __restrict__ bhh,
            float* __restrict__ of) {
    __shared__ __align__(16) float hbuf[2][4][4][PADQ];   // [buf][b][q][64(+4)]
    __shared__ __align__(16) float xs[2][4][PADQ];        // [buf][b][64(+4)]
    __shared__ __align__(16) float gsm[128][4];           // [gate-local][b]
    __shared__ __align__(16) float Wi_s[64 * 128];        // W_ih staging (init only)
    __shared__ __align__(8)  unsigned long long bars[2];

    const int tid  = threadIdx.x;
    const int warp = tid >> 5, lane = tid & 31;
    const int gl = lane & 7, q = lane >> 3;
    const int g  = warp * 8 + gl;          // gate slot 0..127
    const int rank   = blockIdx.x & 7;
    const int batch0 = (blockIdx.x >> 3) * 4;
    const int col = ((g >> 5) << 8) + (rank << 5) + (g & 31);  // column in [0,1024)

    // ---- stage W_ih slice coalesced (init only) ----
    for (int i = tid; i < 8192; i += 512) {
        int k = i >> 7, c = i & 127;
        int cg = ((c >> 5) << 8) + (rank << 5) + (c & 31);
        Wi_s[k * 128 + c] = Wih[(size_t)k * G4 + cg];
    }

    // ---- W_hh registers: k in [q*64, q*64+64), packed as 32 float2 (exact R2) ----
    float2 Wr[32];
    {
        const float* wp = Whh + (size_t)(q * 64) * G4 + col;
#pragma unroll
        for (int j = 0; j < 32; j++) {
            Wr[j].x = wp[(size_t)(2 * j) * G4];
            Wr[j].y = wp[(size_t)(2 * j + 1) * G4];
        }
    }
    // bias folded into xacc, added once (q==0 lanes only)
    float bg = (q == 0) ? (bih[col] + bhh[col]) : 0.0f;

    const uint32_t bar0 = smem_u32(&bars[0]);
    if (tid == 0) {
        mbar_init(bar0, 1);
        mbar_init(bar0 + 8, 1);
        mbar_expect_tx(bar0, 4096);       // armed for first use (t=2)
        mbar_expect_tx(bar0 + 8, 4096);   // armed for first use (t=1)
    }
    // prefetch x for t=0 (xs[0]) and t=1 (xs[1])
    if (tid < 128) {
        int buf = tid >> 6;               // 0 or 1
        int e = tid & 63;
        int b = e >> 4, j = e & 15;
        *reinterpret_cast<float4*>(&xs[buf][b][j * 4]) =
            *reinterpret_cast<const float4*>(g_fuse + ((size_t)(batch0 + b) * SEQ + buf) * FC + j * 4);
    }
    __syncthreads();

    // ---- W_ih registers: k in [q*16, q*16+16) for gate g ----
    float2 Wir[8];
#pragma unroll
    for (int j = 0; j < 8; j++) {
        int k = q * 16 + 2 * j;
        Wir[j].x = Wi_s[k * 128 + g];
        Wir[j].y = Wi_s[(k + 1) * 128 + g];
    }

    asm volatile("barrier.cluster.arrive.aligned;" ::: "memory");
    asm volatile("barrier.cluster.wait.aligned;"   ::: "memory");

    // producer identity (threads 0..127): batch bb, unit ub (exact R2)
    const int bb = tid >> 5, ub = tid & 31;
    const int kglob = (rank << 5) + ub;
    uint32_t dst_loc0 = 0, barloc = bar0;
    if (tid < 128)
        dst_loc0 = smem_u32(&hbuf[0][bb][kglob >> 6][kglob & 63]);

    // ---- xacc for t=0 (from xs[0]) ----
    float xacc[4];
    {
#pragma unroll
        for (int b = 0; b < 4; b++) {
            const float* xp = &xs[0][b][q * 16];
            float2 a = make_float2(bg * 0.5f, bg * 0.5f);   // a.x + a.y = bg
#pragma unroll
            for (int i = 0; i < 8; i++) {
                float2 x2 = *reinterpret_cast<const float2*>(xp + 2 * i);
                a = ffma2(Wir[i], x2, a);
            }
            xacc[b] = a.x + a.y;
        }
    }

    float creg = 0.0f;
    int ph0 = 0, ph1 = 0;

    for (int t = 0; t < SEQ; t++) {
        const int p = t & 1;
        float val[4];
#pragma unroll
        for (int b = 0; b < 4; b++) val[b] = xacc[b];

        if (t > 0) {
            uint32_t barp = bar0 + p * 8;
            int par = p ? ph1 : ph0;
            mbar_wait(barp, par);
            if (p) ph1 ^= 1; else ph0 ^= 1;
            if (tid == 0) mbar_expect_tx(barp, 4096);   // re-arm for t+2

            // ---- recurrent GEMM (exact R2) ----
#pragma unroll
            for (int b = 0; b < 4; b++) {
                float2 acc = make_float2(0.f, 0.f);
                const float* hp = &hbuf[p][b][q][0];
#pragma unroll
                for (int j = 0; j < 16; j++) {
                    float4 h4 = *reinterpret_cast<const float4*>(hp + j * 4);
                    acc = ffma2(Wr[2 * j],     make_float2(h4.x, h4.y), acc);
                    acc = ffma2(Wr[2 * j + 1], make_float2(h4.z, h4.w), acc);
                }
                val[b] += acc.x + acc.y;
            }
        }

        // reduce across quarters (exact R2)
#pragma unroll
        for (int b = 0; b < 4; b++) {
            val[b] += __shfl_xor_sync(0xffffffffu, val[b], 8);
            val[b] += __shfl_xor_sync(0xffffffffu, val[b], 16);
        }
        if (lane < 8) {
            float4 v = make_float4(val[0], val[1], val[2], val[3]);
            *reinterpret_cast<float4*>(&gsm[warp * 8 + lane][0]) = v;
        }
        __syncthreads();

        if (tid < 128) {
            float gi = gsm[ub][bb];
            float gf = gsm[32 + ub][bb];
            float gg = gsm[64 + ub][bb];
            float go = gsm[96 + ub][bb];
            float tg = tanh_(gg);
            creg = sigm(gf) * creg + sigm(gi) * tg;
            float h = sigm(go) * tanh_(creg);

            if (t + 1 < SEQ) {
                uint32_t doff = dst_loc0 + (p ^ 1) * HBUF_BYTES;
                uint32_t boff = barloc + (p ^ 1) * 8;
#pragma unroll
                for (int r = 0; r < 8; r++) {
                    uint32_t rd = mapa_u32(doff, r);
                    uint32_t rb = mapa_u32(boff, r);
                    st_async_f32(rd, h, rb);
                }
            }
            of[(size_t)(batch0 + bb) * (SEQ * HID) + (size_t)t * HID + (rank << 5) + ub] = h;
        } else if (tid < 192 && t + 2 < SEQ) {
            // prefetch x for t+2 into xs[(t+2)&1] = xs[p]
            int e = tid - 128;
            int b = e >> 4, j = e & 15;
            *reinterpret_cast<float4*>(&xs[p][b][j * 4]) =
                *reinterpret_cast<const float4*>(g_fuse + ((size_t)(batch0 + b) * SEQ + (t + 2)) * FC + j * 4);
        }

        // ---- xacc for t+1 from xs[p^1] (regs-only weights; hidden under act/send) ----
        if (t + 1 < SEQ) {
#pragma unroll
            for (int b = 0; b < 4; b++) {
                const float* xp = &xs[p ^ 1][b][q * 16];
                float2 a = make_float2(bg * 0.5f, bg * 0.5f);
#pragma unroll
                for (int i = 0; i < 8; i++) {
                    float2 x2 = *reinterpret_cast<const float2*>(xp + 2 * i);
                    a = ffma2(Wir[i], x2, a);
                }
                xacc[b] = a.x + a.y;
            }
        }
        // no trailing sync (exact R2)
    }

    asm volatile("barrier.cluster.arrive.aligned;" ::: "memory");
    asm volatile("barrier.cluster.wait.aligned;"   ::: "memory");
}

// ---------------- kernel 4: classifier + log_softmax ----------------
__global__ __launch_bounds__(256) void cls_kernel(const float* __restrict__ of,
                                                  const float* __restrict__ W1,
                                                  const float* __restrict__ b1,
                                                  const float* __restrict__ W2,
                                                  const float* __restrict__ b2,
                                                  float* __restrict__ lp) {
    __shared__ float As[2][16][132];
    __shared__ float Bs[2][16][64];

    const int tid = threadIdx.x;
    const int tx = tid & 15, ty = tid >> 4;
    const int row0 = blockIdx.x * 128;

    float b1r[4], w20[4], w21[4];
#pragma unroll
    for (int c = 0; c < 4; c++) {
        int f = tx * 4 + c;
        b1r[c] = b1[f];
        w20[c] = W2[f * 2 + 0];
        w21[c] = W2[f * 2 + 1];
    }
    const float bb0 = b2[0], bb1 = b2[1];

    float2 acc[4][4];
#pragma unroll
    for (int mp = 0; mp < 4; mp++)
#pragma unroll
        for (int c = 0; c < 4; c++) acc[mp][c] = make_float2(0.f, 0.f);

    auto loadA = [&](int s, int kk) {
#pragma unroll
        for (int i = 0; i < 2; i++) {
            int id = tid * 2 + i;
            int m = id >> 2, q = id & 3;
            float4 v = *reinterpret_cast<const float4*>(of + (size_t)(row0 + m) * HID + kk + q * 4);
            As[s][q * 4 + 0][m] = v.x;
            As[s][q * 4 + 1][m] = v.y;
            As[s][q * 4 + 2][m] = v.z;
            As[s][q * 4 + 3][m] = v.w;
        }
    };
    auto loadB = [&](int s, int kk) {
        int k = tid >> 4, q = tid & 15;
        *reinterpret_cast<float4*>(&Bs[s][k][q * 4]) =
            *reinterpret_cast<const float4*>(W1 + (size_t)(kk + k) * 64 + q * 4);
    };

    loadA(0, 0);
    loadB(0, 0);
    __syncthreads();

    for (int ch = 0; ch < 16; ch++) {
        int s = ch & 1;
        if (ch + 1 < 16) { loadA(s ^ 1, (ch + 1) * 16); loadB(s ^ 1, (ch + 1) * 16); }
#pragma unroll
        for (int k = 0; k < 16; k++) {
            float4 b4 = *reinterpret_cast<const float4*>(&Bs[s][k][tx * 4]);
            float4 a0 = *reinterpret_cast<const float4*>(&As[s][k][ty * 8]);
            float4 a1 = *reinterpret_cast<const float4*>(&As[s][k][ty * 8 + 4]);
            float2 aa[4] = { {a0.x, a0.y}, {a0.z, a0.w}, {a1.x, a1.y}, {a1.z, a1.w} };
            float  bb[4] = { b4.x, b4.y, b4.z, b4.w };
#pragma unroll
            for (int c = 0; c < 4; c++) {
                float2 bv = make_float2(bb[c], bb[c]);
#pragma unroll
                for (int mp = 0; mp < 4; mp++) acc[mp][c] = ffma2(aa[mp], bv, acc[mp][c]);
            }
        }
        __syncthreads();
    }

#pragma unroll
    for (int mp = 0; mp < 4; mp++) {
#pragma unroll
        for (int half = 0; half < 2; half++) {
            float p0 = 0.f, p1 = 0.f;
#pragma unroll
            for (int c = 0; c < 4; c++) {
                float vv = half ? acc[mp][c].y : acc[mp][c].x;
                float hd = fmaxf(vv + b1r[c], 0.f);
                p0 += hd * w20[c];
                p1 += hd * w21[c];
            }
#pragma unroll
            for (int s = 1; s < 16; s <<= 1) {
                p0 += __shfl_xor_sync(0xffffffffu, p0, s);
                p1 += __shfl_xor_sync(0xffffffffu, p1, s);
            }
            if ((tid & 15) == 0) {
                float l0 = p0 + bb0, l1 = p1 + bb1;
                float m = fmaxf(l0, l1);
                float lse = m + logf(expf(l0 - m) + expf(l1 - m));
                int row = row0 + ty * 8 + mp * 2 + half;
                lp[row * 2 + 0] = l0 - lse;
                lp[row * 2 + 1] = l1 - lse;
            }
        }
    }
}

// ---------------- kernel 5: gather selected ----------------
__global__ void sel_kernel(const int* __restrict__ ix, const float* __restrict__ of,
                           float* __restrict__ sel) {
    int b = blockIdx.x;
    int t = ix[b];
    sel[b * HID + threadIdx.x] = of[(size_t)b * (SEQ * HID) + (size_t)t * HID + threadIdx.x];
}

// ---------------- launch ----------------
extern "C" void kernel_launch(void* const* d_in, const int* in_sizes, int n_in,
                              void* d_out, int out_size) {
    const float* img = (const float*)d_in[0];
    const float* phr = (const float*)d_in[1];
    const int*   six = (const int*)d_in[3];
    const float* Wc  = (const float*)d_in[4];
    const float* bc  = (const float*)d_in[5];
    const float* Wp  = (const float*)d_in[6];
    const float* bp  = (const float*)d_in[7];
    const float* Wih = (const float*)d_in[8];
    const float* bih = (const float*)d_in[9];
    const float* Whh = (const float*)d_in[10];
    const float* bhh = (const float*)d_in[11];
    const float* W1  = (const float*)d_in[12];
    const float* b1  = (const float*)d_in[13];
    const float* W2  = (const float*)d_in[14];
    const float* b2  = (const float*)d_in[15];

    float* out = (float*)d_out;
    float* lp  = out + OFF_LP;
    float* of  = out + OFF_OF;
    float* sel = out + OFF_SEL;

    emb_kernel <<<64, 64>>>(phr, Wp, bp);
    fuse_kernel<<<256, 256>>>(img, Wc, bc);
    lstm_kernel<<<128, 512>>>(Whh, Wih, bih, bhh, of);
    cls_kernel <<<256, 256>>>(of, W1, b1, W2, b2, lp);
    sel_kernel <<<64, 256>>>(six, of, sel);
}